// round 1
// baseline (speedup 1.0000x reference)
#include <cuda_runtime.h>
#include <math.h>

// NTXentLoss: B=4096, D=256, N=2B=8192, T=0.5
// loss = mean_i( 2 + log(S_i) - s_{i, i^1} ),
//   s_ij = 2 * <zn_i, zn_j>,  S_i = sum_{j != i} exp(s_ij - 2)
// zn rows interleaved: even row r -> zjs[r/2], odd row r -> zis[r/2], L2-normalized.

#define D      256
#define NROWS  8192
#define BT     128   // block tile (rows and cols)
#define KB     16    // K chunk

__device__ float g_zn[NROWS * D];  // 8 MB, normalized interleaved reps
__device__ float g_S[NROWS];       // per-row exp-sums (atomic accum)
__device__ float g_T[NROWS];       // per-row target score s_{i, i^1}

// ---------------------------------------------------------------------------
// Kernel A: interleave + L2-normalize. One block per row, 256 threads (one per
// element of D). Also zeroes g_S for this row (graph replays need a reset).
// ---------------------------------------------------------------------------
__global__ __launch_bounds__(256) void norm_kernel(const float* __restrict__ zis,
                                                   const float* __restrict__ zjs) {
    const int row = blockIdx.x;
    const int tid = threadIdx.x;
    const float* src = (row & 1) ? (zis + (row >> 1) * D) : (zjs + (row >> 1) * D);
    float v = src[tid];
    float sq = v * v;
    #pragma unroll
    for (int o = 16; o > 0; o >>= 1) sq += __shfl_xor_sync(0xffffffffu, sq, o);
    __shared__ float ws[8];
    const int warp = tid >> 5, lane = tid & 31;
    if (lane == 0) ws[warp] = sq;
    __syncthreads();
    float tot = 0.f;
    #pragma unroll
    for (int w = 0; w < 8; w++) tot += ws[w];
    const float norm = fmaxf(sqrtf(tot), 1e-8f);
    g_zn[row * D + tid] = v / norm;
    if (tid == 0) g_S[row] = 0.f;
}

// ---------------------------------------------------------------------------
// Kernel B: fused symmetric GEMM + exp-sum.
// Grid 64x64, block tile 128x128, thread tile 8x8, 256 threads.
// Only upper-triangular tiles (bx >= by) are computed; off-diagonal tiles
// contribute exp-sums to BOTH their row range (i) and column range (j).
// Diagonal tiles also capture the target score s_{i, i^1}.
// ---------------------------------------------------------------------------
__global__ __launch_bounds__(256) void sim_kernel() {
    const int bx = blockIdx.x, by = blockIdx.y;
    if (bx < by) return;                 // symmetry: skip lower triangle
    const int bi = by * BT;              // row-block base (i)
    const int bj = bx * BT;              // col-block base (j)
    const bool diag = (bx == by);

    __shared__ float As[KB][BT];
    __shared__ float Bs[KB][BT];
    __shared__ float sS[BT];             // per-row exp-sum within block
    __shared__ float sC[BT];             // per-col exp-sum within block

    const int tid = threadIdx.x;
    const int tx = tid & 15;             // 16 thread cols
    const int ty = tid >> 4;             // 16 thread rows

    if (tid < BT) { sS[tid] = 0.f; sC[tid] = 0.f; }

    float acc[8][8];
    #pragma unroll
    for (int r = 0; r < 8; r++)
        #pragma unroll
        for (int c = 0; c < 8; c++) acc[r][c] = 0.f;

    for (int kc = 0; kc < D; kc += KB) {
        // Load 128x16 A and B tiles, transposed into smem (As[k][row]).
        #pragma unroll
        for (int l = 0; l < 2; l++) {
            const int idx = l * 256 + tid;          // 0..511
            const int row = idx >> 2;               // 0..127
            const int kq  = idx & 3;                // float4 slot along K
            const float4 va = *(const float4*)&g_zn[(bi + row) * D + kc + kq * 4];
            As[kq * 4 + 0][row] = va.x;
            As[kq * 4 + 1][row] = va.y;
            As[kq * 4 + 2][row] = va.z;
            As[kq * 4 + 3][row] = va.w;
            const float4 vb = *(const float4*)&g_zn[(bj + row) * D + kc + kq * 4];
            Bs[kq * 4 + 0][row] = vb.x;
            Bs[kq * 4 + 1][row] = vb.y;
            Bs[kq * 4 + 2][row] = vb.z;
            Bs[kq * 4 + 3][row] = vb.w;
        }
        __syncthreads();
        #pragma unroll
        for (int k = 0; k < KB; k++) {
            float a[8], b[8];
            #pragma unroll
            for (int r = 0; r < 8; r++) a[r] = As[k][ty * 8 + r];
            #pragma unroll
            for (int c = 0; c < 8; c++) b[c] = Bs[k][tx * 8 + c];
            #pragma unroll
            for (int r = 0; r < 8; r++)
                #pragma unroll
                for (int c = 0; c < 8; c++) acc[r][c] = fmaf(a[r], b[c], acc[r][c]);
        }
        __syncthreads();
    }

    // Epilogue: exp with fixed shift (scores bounded by 2), mask diagonal,
    // capture target on diagonal tiles.
    float rowsum[8], colsum[8];
    #pragma unroll
    for (int r = 0; r < 8; r++) { rowsum[r] = 0.f; colsum[r] = 0.f; }

    #pragma unroll
    for (int r = 0; r < 8; r++) {
        const int gi = bi + ty * 8 + r;
        #pragma unroll
        for (int c = 0; c < 8; c++) {
            const int gj = bj + tx * 8 + c;
            const float s = acc[r][c] * 2.0f;         // /TEMPERATURE
            float e = __expf(s - 2.0f);
            if (gi == gj) e = 0.f;                    // mask self-similarity
            rowsum[r] += e;
            colsum[c] += e;
            if (diag && gj == (gi ^ 1)) g_T[gi] = s;  // positive-pair score
        }
    }

    #pragma unroll
    for (int r = 0; r < 8; r++) atomicAdd(&sS[ty * 8 + r], rowsum[r]);
    if (!diag) {
        #pragma unroll
        for (int c = 0; c < 8; c++) atomicAdd(&sC[tx * 8 + c], colsum[c]);
    }
    __syncthreads();

    if (tid < BT) {
        atomicAdd(&g_S[bi + tid], sS[tid]);
        if (!diag) atomicAdd(&g_S[bj + tid], sC[tid]);
    }
}

// ---------------------------------------------------------------------------
// Kernel C: final reduction to the scalar loss. Single block.
// ---------------------------------------------------------------------------
__global__ __launch_bounds__(256) void loss_kernel(float* __restrict__ out) {
    const int tid = threadIdx.x;
    float sum = 0.f;
    for (int i = tid; i < NROWS; i += 256)
        sum += 2.0f + logf(g_S[i]) - g_T[i];
    #pragma unroll
    for (int o = 16; o > 0; o >>= 1) sum += __shfl_xor_sync(0xffffffffu, sum, o);
    __shared__ float ws[8];
    const int warp = tid >> 5, lane = tid & 31;
    if (lane == 0) ws[warp] = sum;
    __syncthreads();
    if (tid == 0) {
        float tot = 0.f;
        #pragma unroll
        for (int w = 0; w < 8; w++) tot += ws[w];
        out[0] = tot / (float)NROWS;
    }
}

extern "C" void kernel_launch(void* const* d_in, const int* in_sizes, int n_in,
                              void* d_out, int out_size) {
    const float* zis = (const float*)d_in[0];
    const float* zjs = (const float*)d_in[1];
    float* out = (float*)d_out;

    norm_kernel<<<NROWS, 256>>>(zis, zjs);
    dim3 grid(NROWS / BT, NROWS / BT);   // 64 x 64, lower triangle early-exits
    sim_kernel<<<grid, 256>>>();
    loss_kernel<<<1, 256>>>(out);
}

// round 2
// speedup vs baseline: 1.0009x; 1.0009x over previous
#include <cuda_runtime.h>
#include <math.h>

// NTXentLoss: B=4096, D=256, N=2B=8192, T=0.5
// loss = mean_i( 2 + log(S_i) - s_{i, i^1} ),
//   s_ij = 2 * <zn_i, zn_j>,  S_i = sum_{j != i} exp(s_ij - 2)
// zn rows interleaved: even row r -> zjs[r/2], odd row r -> zis[r/2], L2-normalized.

#define D      256
#define NROWS  8192
#define BT     128   // block tile (rows and cols)
#define KB     16    // K chunk

__device__ float g_zn[NROWS * D];  // 8 MB, normalized interleaved reps
__device__ float g_S[NROWS];       // per-row exp-sums (atomic accum)
__device__ float g_T[NROWS];       // per-row target score s_{i, i^1}

// ---------------------------------------------------------------------------
// Kernel A: interleave + L2-normalize. One block per row, 256 threads (one per
// element of D). Also zeroes g_S for this row (graph replays need a reset).
// ---------------------------------------------------------------------------
__global__ __launch_bounds__(256) void norm_kernel(const float* __restrict__ zis,
                                                   const float* __restrict__ zjs) {
    const int row = blockIdx.x;
    const int tid = threadIdx.x;
    const float* src = (row & 1) ? (zis + (row >> 1) * D) : (zjs + (row >> 1) * D);
    float v = src[tid];
    float sq = v * v;
    #pragma unroll
    for (int o = 16; o > 0; o >>= 1) sq += __shfl_xor_sync(0xffffffffu, sq, o);
    __shared__ float ws[8];
    const int warp = tid >> 5, lane = tid & 31;
    if (lane == 0) ws[warp] = sq;
    __syncthreads();
    float tot = 0.f;
    #pragma unroll
    for (int w = 0; w < 8; w++) tot += ws[w];
    const float norm = fmaxf(sqrtf(tot), 1e-8f);
    g_zn[row * D + tid] = v / norm;
    if (tid == 0) g_S[row] = 0.f;
}

// ---------------------------------------------------------------------------
// Kernel B: fused symmetric GEMM + exp-sum.
// Grid 64x64, block tile 128x128, thread tile 8x8, 256 threads.
// Only upper-triangular tiles (bx >= by) are computed; off-diagonal tiles
// contribute exp-sums to BOTH their row range (i) and column range (j).
// Diagonal tiles also capture the target score s_{i, i^1}.
// ---------------------------------------------------------------------------
__global__ __launch_bounds__(256) void sim_kernel() {
    const int bx = blockIdx.x, by = blockIdx.y;
    if (bx < by) return;                 // symmetry: skip lower triangle
    const int bi = by * BT;              // row-block base (i)
    const int bj = bx * BT;              // col-block base (j)
    const bool diag = (bx == by);

    __shared__ float As[KB][BT];
    __shared__ float Bs[KB][BT];
    __shared__ float sS[BT];             // per-row exp-sum within block
    __shared__ float sC[BT];             // per-col exp-sum within block

    const int tid = threadIdx.x;
    const int tx = tid & 15;             // 16 thread cols
    const int ty = tid >> 4;             // 16 thread rows

    if (tid < BT) { sS[tid] = 0.f; sC[tid] = 0.f; }

    float acc[8][8];
    #pragma unroll
    for (int r = 0; r < 8; r++)
        #pragma unroll
        for (int c = 0; c < 8; c++) acc[r][c] = 0.f;

    for (int kc = 0; kc < D; kc += KB) {
        // Load 128x16 A and B tiles, transposed into smem (As[k][row]).
        #pragma unroll
        for (int l = 0; l < 2; l++) {
            const int idx = l * 256 + tid;          // 0..511
            const int row = idx >> 2;               // 0..127
            const int kq  = idx & 3;                // float4 slot along K
            const float4 va = *(const float4*)&g_zn[(bi + row) * D + kc + kq * 4];
            As[kq * 4 + 0][row] = va.x;
            As[kq * 4 + 1][row] = va.y;
            As[kq * 4 + 2][row] = va.z;
            As[kq * 4 + 3][row] = va.w;
            const float4 vb = *(const float4*)&g_zn[(bj + row) * D + kc + kq * 4];
            Bs[kq * 4 + 0][row] = vb.x;
            Bs[kq * 4 + 1][row] = vb.y;
            Bs[kq * 4 + 2][row] = vb.z;
            Bs[kq * 4 + 3][row] = vb.w;
        }
        __syncthreads();
        #pragma unroll
        for (int k = 0; k < KB; k++) {
            float a[8], b[8];
            #pragma unroll
            for (int r = 0; r < 8; r++) a[r] = As[k][ty * 8 + r];
            #pragma unroll
            for (int c = 0; c < 8; c++) b[c] = Bs[k][tx * 8 + c];
            #pragma unroll
            for (int r = 0; r < 8; r++)
                #pragma unroll
                for (int c = 0; c < 8; c++) acc[r][c] = fmaf(a[r], b[c], acc[r][c]);
        }
        __syncthreads();
    }

    // Epilogue: exp with fixed shift (scores bounded by 2), mask diagonal,
    // capture target on diagonal tiles.
    float rowsum[8], colsum[8];
    #pragma unroll
    for (int r = 0; r < 8; r++) { rowsum[r] = 0.f; colsum[r] = 0.f; }

    #pragma unroll
    for (int r = 0; r < 8; r++) {
        const int gi = bi + ty * 8 + r;
        #pragma unroll
        for (int c = 0; c < 8; c++) {
            const int gj = bj + tx * 8 + c;
            const float s = acc[r][c] * 2.0f;         // /TEMPERATURE
            float e = __expf(s - 2.0f);
            if (gi == gj) e = 0.f;                    // mask self-similarity
            rowsum[r] += e;
            colsum[c] += e;
            if (diag && gj == (gi ^ 1)) g_T[gi] = s;  // positive-pair score
        }
    }

    #pragma unroll
    for (int r = 0; r < 8; r++) atomicAdd(&sS[ty * 8 + r], rowsum[r]);
    if (!diag) {
        #pragma unroll
        for (int c = 0; c < 8; c++) atomicAdd(&sC[tx * 8 + c], colsum[c]);
    }
    __syncthreads();

    if (tid < BT) {
        atomicAdd(&g_S[bi + tid], sS[tid]);
        if (!diag) atomicAdd(&g_S[bj + tid], sC[tid]);
    }
}

// ---------------------------------------------------------------------------
// Kernel C: final reduction to the scalar loss. Single block.
// ---------------------------------------------------------------------------
__global__ __launch_bounds__(256) void loss_kernel(float* __restrict__ out) {
    const int tid = threadIdx.x;
    float sum = 0.f;
    for (int i = tid; i < NROWS; i += 256)
        sum += 2.0f + logf(g_S[i]) - g_T[i];
    #pragma unroll
    for (int o = 16; o > 0; o >>= 1) sum += __shfl_xor_sync(0xffffffffu, sum, o);
    __shared__ float ws[8];
    const int warp = tid >> 5, lane = tid & 31;
    if (lane == 0) ws[warp] = sum;
    __syncthreads();
    if (tid == 0) {
        float tot = 0.f;
        #pragma unroll
        for (int w = 0; w < 8; w++) tot += ws[w];
        out[0] = tot / (float)NROWS;
    }
}

extern "C" void kernel_launch(void* const* d_in, const int* in_sizes, int n_in,
                              void* d_out, int out_size) {
    const float* zis = (const float*)d_in[0];
    const float* zjs = (const float*)d_in[1];
    float* out = (float*)d_out;

    norm_kernel<<<NROWS, 256>>>(zis, zjs);
    dim3 grid(NROWS / BT, NROWS / BT);   // 64 x 64, lower triangle early-exits
    sim_kernel<<<grid, 256>>>();
    loss_kernel<<<1, 256>>>(out);
}